// round 14
// baseline (speedup 1.0000x reference)
#include <cuda_runtime.h>
#include <cstdint>

// Problem constants (fixed by reference)
#define BS   1024
#define NSEQ 32
#define NBOX 128
#define NCTX 5
#define MAXC 4

// Task descriptor: the fully-resolved index chain for one (it,b) task.
struct alignas(16) Desc {
    int   r;        // parent row, or -1 if invalid task
    int   c0;       // first child row
    int   e0;       // edge row for spo/roi gather
    float cv0;      // child_valid[0]
    int   cols[5];  // scatter columns ctx[fs, fe, 0, k]
    int   pad[3];
};
__device__ Desc g_desc[32768];   // up to L=32 iterations x BS tasks

// ---------------- Prologue: resolve index chains, one thread per task ---------
__global__ __launch_bounds__(256) void build_desc_kernel(
    const int*   __restrict__ ctx,   // [BS,NSEQ,NBOX,NCTX]
    const int*   __restrict__ pidx,  // [L,BS]
    const float* __restrict__ pval,  // [L,BS]
    const int*   __restrict__ cidx,  // [L,BS,MAXC]
    const float* __restrict__ cval,  // [L,BS,MAXC]
    const int*   __restrict__ eidx,  // [L,BS,MAXC]
    const int*   __restrict__ fsmp,  // [L,BS]
    const int*   __restrict__ fslt,  // [L,BS]
    int n_tasks)
{
    const int task = blockIdx.x * blockDim.x + threadIdx.x;
    if (task >= n_tasks) return;
    const int it = task >> 10;          // / BS
    const int b  = task & (BS - 1);     // % BS
    const int base = it * BS + b;

    Desc d;
    const float pv = pval[base];
    if (pv <= 0.f) {
        d.r = -1; d.c0 = 0; d.e0 = 0; d.cv0 = 0.f;
        #pragma unroll
        for (int k = 0; k < 5; k++) d.cols[k] = 0;
        d.pad[0] = d.pad[1] = d.pad[2] = 0;
        g_desc[task] = d;
        return;
    }
    d.r   = pidx[base];
    d.c0  = cidx[base * MAXC + 0];
    d.cv0 = cval[base * MAXC + 0];
    d.e0  = eidx[base * MAXC + 0];
    const int fs = fsmp[base];
    const int fl = fslt[base];
    const int fe = eidx[(it * BS + fs) * MAXC + fl];
    const int* cbase = ctx + (((size_t)fs * NSEQ + fe) * NBOX) * NCTX;
    #pragma unroll
    for (int k = 0; k < 5; k++) d.cols[k] = cbase[k];
    d.pad[0] = d.pad[1] = d.pad[2] = 0;
    g_desc[task] = d;
}

// ---------------- Main kernel: 384 threads = 8 compute + 4 copy-group warps ---
// Fully parallel: children always have larger indices than parents; parents
// ascend & are unique per batch, so every read in the sequential reference
// sees the ORIGINAL ent_attn. Parent rows are written only by compute warps,
// non-parent rows only by copy warps (exactly once each).
__global__ __launch_bounds__(384) void topdown_main_kernel(
    const float* __restrict__ ent,   // [BS,NSEQ,NBOX]
    const float* __restrict__ spo,   // [BS,NSEQ,NBOX,NCTX]
    const float* __restrict__ roi,   // [BS,NSEQ,NBOX,NCTX]
    const int*   __restrict__ rcls,  // [BS,NBOX]
    const float* __restrict__ w,     // [BS,NSEQ,NBOX]
    const int*   __restrict__ pidx,  // [L,BS]
    const float* __restrict__ pval,  // [L,BS]
    float*       __restrict__ out,   // [BS,NSEQ,NBOX]
    int n_tasks, int L)
{
    const int wid  = threadIdx.x >> 5;
    const int lane = threadIdx.x & 31;

    if (wid >= 8) {
        // ------- copy warp: 4 rows per warp (rows 4*idx .. 4*idx+3) -------
        const int idx = blockIdx.x * 4 + (wid - 8);
        if (idx >= BS * (NSEQ / 4)) return;
        const int b = idx >> 3;         // / 8
        const int g = idx & 7;          // % 8 -> rows 4g..4g+3

        // parent-row bitmask for batch b (lane = iteration)
        unsigned bit = 0;
        if (lane < L) {
            const int   p = pidx[lane * BS + b];
            const float v = pval[lane * BS + b];
            if (v > 0.f) bit = 1u << p;
        }
        const unsigned rowmask = __reduce_or_sync(0xffffffffu, bit);

        const float4* src = (const float4*)(ent + (((size_t)b * NSEQ + 4 * g) * NBOX));
        float4*       dst = (float4*)(out + (((size_t)b * NSEQ + 4 * g) * NBOX));

        bool   nd[4];
        float4 vv[4];
        #pragma unroll
        for (int q = 0; q < 4; q++) {
            nd[q] = !((rowmask >> (4 * g + q)) & 1u);
            if (nd[q]) vv[q] = __ldcs(src + q * 32 + lane);   // front-batched
        }
        #pragma unroll
        for (int q = 0; q < 4; q++)
            if (nd[q]) __stcs(dst + q * 32 + lane, vv[q]);
        return;
    }

    // ---------------- compute warp: one per (it, b) task ----------------
    const int task = blockIdx.x * 8 + wid;
    if (task >= n_tasks) return;
    const int b = task & (BS - 1);

    // broadcast descriptor loads (uniform address, L2-hot)
    const float4* dp = (const float4*)&g_desc[task];
    const float4 d0 = __ldg(dp + 0);
    const float4 d1 = __ldg(dp + 1);
    const float4 d2 = __ldg(dp + 2);

    const int   r   = __float_as_int(d0.x);
    if (r < 0) return;
    const int   c0  = __float_as_int(d0.y);
    const int   e0  = __float_as_int(d0.z);
    const float cv0 = d0.w;
    int cols[NCTX];
    cols[0] = __float_as_int(d1.x);
    cols[1] = __float_as_int(d1.y);
    cols[2] = __float_as_int(d1.z);
    cols[3] = __float_as_int(d1.w);
    cols[4] = __float_as_int(d2.x);

    // --- transfer[k] = cv0 * sum_box ent[b,c0,box]*cls*spo[b,e0,box,k]*roi[b,e0,box,k] + 1e-6 ---
    const float* entc   = ent  + ((size_t)b * NSEQ + c0) * NBOX;
    const float* spor   = spo  + ((size_t)b * NSEQ + e0) * NBOX * NCTX;
    const float* roir   = roi  + ((size_t)b * NSEQ + e0) * NBOX * NCTX;
    const int*   clsrow = rcls + (size_t)b * NBOX;

    float t0 = 0.f, t1 = 0.f, t2 = 0.f, t3 = 0.f, t4 = 0.f;
    #pragma unroll
    for (int q = 0; q < NBOX / 32; q++) {
        const int box = lane + q * 32;
        float ca = entc[box];
        if (clsrow[box] == -1) ca = 0.f;
        const float* s  = spor + box * NCTX;
        const float* mr = roir + box * NCTX;
        t0 += ca * __ldcs(s + 0) * __ldcs(mr + 0);
        t1 += ca * __ldcs(s + 1) * __ldcs(mr + 1);
        t2 += ca * __ldcs(s + 2) * __ldcs(mr + 2);
        t3 += ca * __ldcs(s + 3) * __ldcs(mr + 3);
        t4 += ca * __ldcs(s + 4) * __ldcs(mr + 4);
    }
    #pragma unroll
    for (int o = 16; o > 0; o >>= 1) {
        t0 += __shfl_xor_sync(0xffffffffu, t0, o);
        t1 += __shfl_xor_sync(0xffffffffu, t1, o);
        t2 += __shfl_xor_sync(0xffffffffu, t2, o);
        t3 += __shfl_xor_sync(0xffffffffu, t3, o);
        t4 += __shfl_xor_sync(0xffffffffu, t4, o);
    }
    float tr[NCTX];
    tr[0] = cv0 * t0 + 1e-6f;
    tr[1] = cv0 * t1 + 1e-6f;
    tr[2] = cv0 * t2 + 1e-6f;
    tr[3] = cv0 * t3 + 1e-6f;
    tr[4] = cv0 * t4 + 1e-6f;

    // --- row update: each lane owns 4 consecutive boxes of the parent row ---
    const float4 sub = ((const float4*)(ent + ((size_t)b * NSEQ + r) * NBOX))[lane];
    const float4 wv  = __ldcs(((const float4*)(w + ((size_t)b * NSEQ + r) * NBOX)) + lane);
    const int4   cl  = ((const int4*)clsrow)[lane];

    float su[4]  = {sub.x, sub.y, sub.z, sub.w};
    float wa[4]  = {wv.x, wv.y, wv.z, wv.w};
    int   cla[4] = {cl.x, cl.y, cl.z, cl.w};

    float u[4];
    float mx = 0.f;
    #pragma unroll
    for (int q = 0; q < 4; q++) {
        const int box = lane * 4 + q;
        float add = 1e-6f;
        #pragma unroll
        for (int k = 0; k < NCTX; k++)
            if (cols[k] == box) add = tr[k];
        u[q] = su[q] + add * wa[q];
        mx = fmaxf(mx, fabsf(u[q]));
    }
    #pragma unroll
    for (int o = 16; o > 0; o >>= 1)
        mx = fmaxf(mx, __shfl_xor_sync(0xffffffffu, mx, o));
    const float d = (mx <= 1.f) ? 1.f : mx;

    float rr[4];
    #pragma unroll
    for (int q = 0; q < 4; q++) {
        float vvv = u[q] / d;
        if (cla[q] == -1) vvv = -1.0f;
        rr[q] = vvv;
    }
    float4 res;
    res.x = rr[0]; res.y = rr[1]; res.z = rr[2]; res.w = rr[3];
    __stcs(((float4*)(out + ((size_t)b * NSEQ + r) * NBOX)) + lane, res);
}

extern "C" void kernel_launch(void* const* d_in, const int* in_sizes, int n_in,
                              void* d_out, int out_size) {
    const float* ent  = (const float*)d_in[0];   // ent_attn
    const int*   ctx  = (const int*)  d_in[2];   // ctx_idx_adjusted
    const float* spo  = (const float*)d_in[1];   // spo_attn
    const float* roi  = (const float*)d_in[3];   // roi_mask
    const int*   rcls = (const int*)  d_in[4];   // roi_cls
    const float* w    = (const float*)d_in[5];   // weight_on_children
    const int*   pidx = (const int*)  d_in[6];   // parent_idx [L,BS]
    const float* pval = (const float*)d_in[7];   // parent_valid
    const int*   cidx = (const int*)  d_in[8];   // child_idx
    const float* cval = (const float*)d_in[9];   // child_valid
    const int*   eidx = (const int*)  d_in[10];  // edge_idx
    const int*   fsmp = (const int*)  d_in[11];  // flat_sample
    const int*   fslt = (const int*)  d_in[12];  // flat_slot

    const int L = in_sizes[6] / BS;
    const int n_tasks = L * BS;

    // Prologue: resolve index chains (thread-parallel)
    build_desc_kernel<<<(n_tasks + 255) / 256, 256>>>(
        ctx, pidx, pval, cidx, cval, eidx, fsmp, fslt, n_tasks);

    // Main: 8 compute warps + 4 copy-group warps per 384-thread block
    const int blocks_compute = (n_tasks + 7) / 8;
    const int blocks_copy    = (BS * (NSEQ / 4) + 3) / 4;   // 2048
    const int blocks = blocks_compute > blocks_copy ? blocks_compute : blocks_copy;

    topdown_main_kernel<<<blocks, 384>>>(
        ent, spo, roi, rcls, w, pidx, pval,
        (float*)d_out, n_tasks, L);
}

// round 15
// speedup vs baseline: 1.0052x; 1.0052x over previous
#include <cuda_runtime.h>
#include <cstdint>

// Problem constants (fixed by reference)
#define BS   1024
#define NSEQ 32
#define NBOX 128
#define NCTX 5
#define MAXC 4

// Single kernel, 384 threads/block:
//   warps 0-7  : compute task  bid*8 + wid        (one per (it,b), pval>0)
//   warps 8-11 : copy group    bid*4 + (wid-8)    (4 rows each, skip parents)
// Compute warps resolve the index chain inline but depth-ordered, so every
// load is issued at the earliest cycle its address is known: 1-hop index
// loads -> parent-row/w/cls + fe -> child/spo/roi rows + cols -> reduce
// (row latencies hide under the reduction) -> update.
//
// Fully parallel: children always have larger indices than parents; parents
// ascend & are unique per batch, so every read in the sequential reference
// sees the ORIGINAL ent_attn. Parent rows are written only by compute warps,
// non-parent rows only by copy warps (exactly once each).
__global__ __launch_bounds__(384) void topdown_fused_kernel(
    const float* __restrict__ ent,   // [BS,NSEQ,NBOX]
    const float* __restrict__ spo,   // [BS,NSEQ,NBOX,NCTX]
    const int*   __restrict__ ctx,   // [BS,NSEQ,NBOX,NCTX]
    const float* __restrict__ roi,   // [BS,NSEQ,NBOX,NCTX]
    const int*   __restrict__ rcls,  // [BS,NBOX]
    const float* __restrict__ w,     // [BS,NSEQ,NBOX]
    const int*   __restrict__ pidx,  // [L,BS]
    const float* __restrict__ pval,  // [L,BS]
    const int*   __restrict__ cidx,  // [L,BS,MAXC]
    const float* __restrict__ cval,  // [L,BS,MAXC]
    const int*   __restrict__ eidx,  // [L,BS,MAXC]
    const int*   __restrict__ fsmp,  // [L,BS]
    const int*   __restrict__ fslt,  // [L,BS]
    float*       __restrict__ out,   // [BS,NSEQ,NBOX]
    int n_tasks, int L)
{
    const int wid  = threadIdx.x >> 5;
    const int lane = threadIdx.x & 31;

    if (wid >= 8) {
        // ------- copy warp: 4 rows per warp (rows 4g..4g+3 of batch b) -------
        const int idx = blockIdx.x * 4 + (wid - 8);
        if (idx >= BS * (NSEQ / 4)) return;
        const int b = idx >> 3;         // / 8
        const int g = idx & 7;          // % 8

        // parent-row bitmask for batch b (lane = iteration)
        unsigned bit = 0;
        if (lane < L) {
            const int   p = pidx[lane * BS + b];
            const float v = pval[lane * BS + b];
            if (v > 0.f) bit = 1u << p;
        }
        const unsigned rowmask = __reduce_or_sync(0xffffffffu, bit);

        const float4* src = (const float4*)(ent + (((size_t)b * NSEQ + 4 * g) * NBOX));
        float4*       dst = (float4*)(out + (((size_t)b * NSEQ + 4 * g) * NBOX));

        bool   nd[4];
        float4 vv[4];
        #pragma unroll
        for (int q = 0; q < 4; q++) {
            nd[q] = !((rowmask >> (4 * g + q)) & 1u);
            if (nd[q]) vv[q] = src[q * 32 + lane];   // front-batched, L2-cacheable
        }
        #pragma unroll
        for (int q = 0; q < 4; q++)
            if (nd[q]) __stcs(dst + q * 32 + lane, vv[q]);
        return;
    }

    // ---------------- compute warp: one per (it, b) task ----------------
    const int task = blockIdx.x * 8 + wid;
    if (task >= n_tasks) return;
    const int it = task >> 10;          // / BS
    const int b  = task & (BS - 1);     // % BS
    const int base = it * BS + b;

    // --- hop 1: all base-index loads (independent, issued together) ---
    const float pv  = pval[base];
    const int   r   = pidx[base];
    const int   c0  = cidx[base * MAXC + 0];
    const float cv0 = cval[base * MAXC + 0];
    const int   e0  = eidx[base * MAXC + 0];
    const int   fs  = fsmp[base];
    const int   fl  = fslt[base];
    if (pv <= 0.f) return;              // warp-uniform

    // --- hop 2 (issued ASAP): parent row, weights, cls; fe index ---
    const int* clsrow = rcls + (size_t)b * NBOX;
    const float4 sub = ((const float4*)(ent + ((size_t)b * NSEQ + r) * NBOX))[lane];
    const float4 wv  = __ldcs(((const float4*)(w + ((size_t)b * NSEQ + r) * NBOX)) + lane);
    const int4   cl  = ((const int4*)clsrow)[lane];
    const int    fe  = eidx[(it * BS + fs) * MAXC + fl];

    // --- hop 3 (issued before reduction, consumed after): scatter columns ---
    int cols[NCTX];
    const int* cbase = ctx + (((size_t)fs * NSEQ + fe) * NBOX) * NCTX;
    #pragma unroll
    for (int k = 0; k < NCTX; k++) cols[k] = cbase[k];

    // --- transfer[k] = cv0 * sum_box ent[b,c0,box]*cls*spo[b,e0,box,k]*roi[b,e0,box,k] + 1e-6 ---
    const float* entc = ent + ((size_t)b * NSEQ + c0) * NBOX;
    const float* spor = spo + ((size_t)b * NSEQ + e0) * NBOX * NCTX;
    const float* roir = roi + ((size_t)b * NSEQ + e0) * NBOX * NCTX;

    float t0 = 0.f, t1 = 0.f, t2 = 0.f, t3 = 0.f, t4 = 0.f;
    #pragma unroll
    for (int q = 0; q < NBOX / 32; q++) {
        const int box = lane + q * 32;
        float ca = entc[box];
        if (clsrow[box] == -1) ca = 0.f;
        const float* s  = spor + box * NCTX;
        const float* mr = roir + box * NCTX;
        t0 += ca * __ldcs(s + 0) * __ldcs(mr + 0);
        t1 += ca * __ldcs(s + 1) * __ldcs(mr + 1);
        t2 += ca * __ldcs(s + 2) * __ldcs(mr + 2);
        t3 += ca * __ldcs(s + 3) * __ldcs(mr + 3);
        t4 += ca * __ldcs(s + 4) * __ldcs(mr + 4);
    }
    #pragma unroll
    for (int o = 16; o > 0; o >>= 1) {
        t0 += __shfl_xor_sync(0xffffffffu, t0, o);
        t1 += __shfl_xor_sync(0xffffffffu, t1, o);
        t2 += __shfl_xor_sync(0xffffffffu, t2, o);
        t3 += __shfl_xor_sync(0xffffffffu, t3, o);
        t4 += __shfl_xor_sync(0xffffffffu, t4, o);
    }
    float tr[NCTX];
    tr[0] = cv0 * t0 + 1e-6f;
    tr[1] = cv0 * t1 + 1e-6f;
    tr[2] = cv0 * t2 + 1e-6f;
    tr[3] = cv0 * t3 + 1e-6f;
    tr[4] = cv0 * t4 + 1e-6f;

    // --- row update: each lane owns 4 consecutive boxes of the parent row ---
    float su[4]  = {sub.x, sub.y, sub.z, sub.w};
    float wa[4]  = {wv.x, wv.y, wv.z, wv.w};
    int   cla[4] = {cl.x, cl.y, cl.z, cl.w};

    float u[4];
    float mx = 0.f;
    #pragma unroll
    for (int q = 0; q < 4; q++) {
        const int box = lane * 4 + q;
        float add = 1e-6f;
        #pragma unroll
        for (int k = 0; k < NCTX; k++)
            if (cols[k] == box) add = tr[k];
        u[q] = su[q] + add * wa[q];
        mx = fmaxf(mx, fabsf(u[q]));
    }
    #pragma unroll
    for (int o = 16; o > 0; o >>= 1)
        mx = fmaxf(mx, __shfl_xor_sync(0xffffffffu, mx, o));
    const float d = (mx <= 1.f) ? 1.f : mx;

    float rr[4];
    #pragma unroll
    for (int q = 0; q < 4; q++) {
        float vvv = u[q] / d;
        if (cla[q] == -1) vvv = -1.0f;
        rr[q] = vvv;
    }
    float4 res;
    res.x = rr[0]; res.y = rr[1]; res.z = rr[2]; res.w = rr[3];
    __stcs(((float4*)(out + ((size_t)b * NSEQ + r) * NBOX)) + lane, res);
}

extern "C" void kernel_launch(void* const* d_in, const int* in_sizes, int n_in,
                              void* d_out, int out_size) {
    const float* ent  = (const float*)d_in[0];   // ent_attn
    const float* spo  = (const float*)d_in[1];   // spo_attn
    const int*   ctx  = (const int*)  d_in[2];   // ctx_idx_adjusted
    const float* roi  = (const float*)d_in[3];   // roi_mask
    const int*   rcls = (const int*)  d_in[4];   // roi_cls
    const float* w    = (const float*)d_in[5];   // weight_on_children
    const int*   pidx = (const int*)  d_in[6];   // parent_idx [L,BS]
    const float* pval = (const float*)d_in[7];   // parent_valid
    const int*   cidx = (const int*)  d_in[8];   // child_idx
    const float* cval = (const float*)d_in[9];   // child_valid
    const int*   eidx = (const int*)  d_in[10];  // edge_idx
    const int*   fsmp = (const int*)  d_in[11];  // flat_sample
    const int*   fslt = (const int*)  d_in[12];  // flat_slot

    const int L = in_sizes[6] / BS;
    const int n_tasks = L * BS;

    // 8 compute warps + 4 copy-group warps (4 rows each) per 384-thread block
    const int blocks_compute = (n_tasks + 7) / 8;
    const int blocks_copy    = (BS * (NSEQ / 4) + 3) / 4;   // 2048
    const int blocks = blocks_compute > blocks_copy ? blocks_compute : blocks_copy;

    topdown_fused_kernel<<<blocks, 384>>>(
        ent, spo, ctx, roi, rcls, w,
        pidx, pval, cidx, cval, eidx, fsmp, fslt,
        (float*)d_out, n_tasks, L);
}

// round 16
// speedup vs baseline: 1.1735x; 1.1674x over previous
#include <cuda_runtime.h>
#include <cstdint>

// Problem constants (fixed by reference)
#define BS   1024
#define NSEQ 32
#define NBOX 128
#define NCTX 5
#define MAXC 4

// One warp per (it,b) task; each warp ALSO copies its share of rows
// [32*it/L, 32*(it+1)/L) of batch b (partitions all rows across it=0..L-1).
// Warp pipeline: issue hop-1 index loads + ballot column + copy-row loads at
// t0 (all independent) -> ballot -> copy stores (their wait hides the index
// wait) -> compute section (R8's 32-reg body) with the chain already hot.
// Copy rows are LOADED unconditionally (issue at t0) and STORED only if not
// a parent row; parent rows are written exclusively by their compute warp.
//
// Fully parallel: children always have larger indices than parents; parents
// ascend & are unique per batch, so every read in the sequential reference
// sees the ORIGINAL ent_attn.
__global__ __launch_bounds__(256) void topdown_fused_kernel(
    const float* __restrict__ ent,   // [BS,NSEQ,NBOX]
    const float* __restrict__ spo,   // [BS,NSEQ,NBOX,NCTX]
    const int*   __restrict__ ctx,   // [BS,NSEQ,NBOX,NCTX]
    const float* __restrict__ roi,   // [BS,NSEQ,NBOX,NCTX]
    const int*   __restrict__ rcls,  // [BS,NBOX]
    const float* __restrict__ w,     // [BS,NSEQ,NBOX]
    const int*   __restrict__ pidx,  // [L,BS]
    const float* __restrict__ pval,  // [L,BS]
    const int*   __restrict__ cidx,  // [L,BS,MAXC]
    const float* __restrict__ cval,  // [L,BS,MAXC]
    const int*   __restrict__ eidx,  // [L,BS,MAXC]
    const int*   __restrict__ fsmp,  // [L,BS]
    const int*   __restrict__ fslt,  // [L,BS]
    float*       __restrict__ out,   // [BS,NSEQ,NBOX]
    int n_tasks, int L)
{
    const int warp = (blockIdx.x * blockDim.x + threadIdx.x) >> 5;
    const int lane = threadIdx.x & 31;
    if (warp >= n_tasks) return;
    const int it = warp >> 10;          // / BS
    const int b  = warp & (BS - 1);     // % BS
    const int base = it * BS + b;

    // ---- t0: hop-1 index loads (independent; issued together) ----
    const float pv  = pval[base];
    const int   r   = pidx[base];
    const int   c0  = cidx[base * MAXC + 0];
    const float cv0 = cval[base * MAXC + 0];
    const int   e0  = eidx[base * MAXC + 0];
    const int   fs  = fsmp[base];
    const int   fl  = fslt[base];

    // ballot column (lane = iteration)
    int   pb = -1;
    float vb = 0.f;
    if (lane < L) {
        pb = pidx[lane * BS + b];
        vb = pval[lane * BS + b];
    }

    // ---- t0: copy-row loads, unconditional (rows r0..r1-1 of batch b) ----
    const int r0 = (NSEQ * it) / L;
    const int r1 = (NSEQ * (it + 1)) / L;
    const float4* entb = (const float4*)(ent + (size_t)b * NSEQ * NBOX);
    float4*       outb = (float4*)((float*)out + (size_t)b * NSEQ * NBOX);

    float4 cvv[4];
    #pragma unroll
    for (int q = 0; q < 4; q++) {
        const int rr = r0 + q;
        if (rr < r1) cvv[q] = entb[rr * 32 + lane];
    }

    // ---- parent-row bitmask (waits only on the ballot column) ----
    unsigned bit = 0;
    if (lane < L && vb > 0.f) bit = 1u << pb;
    const unsigned rowmask = __reduce_or_sync(0xffffffffu, bit);

    // ---- copy stores: wait for copy data overlaps hop-1 index wait ----
    #pragma unroll
    for (int q = 0; q < 4; q++) {
        const int rr = r0 + q;
        if (rr < r1 && !((rowmask >> rr) & 1u))
            __stcs(outb + rr * 32 + lane, cvv[q]);
    }
    // safety tail for L < 8 (not expected in this dataset)
    for (int rr = r0 + 4; rr < r1; rr++) {
        if (!((rowmask >> rr) & 1u)) {
            const float4 v = entb[rr * 32 + lane];
            __stcs(outb + rr * 32 + lane, v);
        }
    }

    if (pv <= 0.f) return;              // warp-uniform; copy duty done

    // ---- hop 2: fe; addresses for all row reads (indices already hot) ----
    const int fe = eidx[(it * BS + fs) * MAXC + fl];

    const float* entc   = ent  + ((size_t)b * NSEQ + c0) * NBOX;
    const float* spor   = spo  + ((size_t)b * NSEQ + e0) * NBOX * NCTX;
    const float* roir   = roi  + ((size_t)b * NSEQ + e0) * NBOX * NCTX;
    const int*   clsrow = rcls + (size_t)b * NBOX;

    // hop 3 issued before the reduction, consumed after it
    int cols[NCTX];
    const int* cbase = ctx + (((size_t)fs * NSEQ + fe) * NBOX) * NCTX;
    #pragma unroll
    for (int k = 0; k < NCTX; k++) cols[k] = cbase[k];

    // --- transfer[k] = cv0 * sum_box ent[b,c0,box]*cls*spo[b,e0,box,k]*roi[b,e0,box,k] + 1e-6 ---
    float t0 = 0.f, t1 = 0.f, t2 = 0.f, t3 = 0.f, t4 = 0.f;
    #pragma unroll
    for (int q = 0; q < NBOX / 32; q++) {
        const int box = lane + q * 32;
        float ca = entc[box];
        if (clsrow[box] == -1) ca = 0.f;
        const float* s  = spor + box * NCTX;
        const float* mr = roir + box * NCTX;
        t0 += ca * __ldcs(s + 0) * __ldcs(mr + 0);
        t1 += ca * __ldcs(s + 1) * __ldcs(mr + 1);
        t2 += ca * __ldcs(s + 2) * __ldcs(mr + 2);
        t3 += ca * __ldcs(s + 3) * __ldcs(mr + 3);
        t4 += ca * __ldcs(s + 4) * __ldcs(mr + 4);
    }
    #pragma unroll
    for (int o = 16; o > 0; o >>= 1) {
        t0 += __shfl_xor_sync(0xffffffffu, t0, o);
        t1 += __shfl_xor_sync(0xffffffffu, t1, o);
        t2 += __shfl_xor_sync(0xffffffffu, t2, o);
        t3 += __shfl_xor_sync(0xffffffffu, t3, o);
        t4 += __shfl_xor_sync(0xffffffffu, t4, o);
    }
    float tr[NCTX];
    tr[0] = cv0 * t0 + 1e-6f;
    tr[1] = cv0 * t1 + 1e-6f;
    tr[2] = cv0 * t2 + 1e-6f;
    tr[3] = cv0 * t3 + 1e-6f;
    tr[4] = cv0 * t4 + 1e-6f;

    // --- row update: each lane owns 4 consecutive boxes of the parent row ---
    const float4 sub = entb[r * 32 + lane];
    const float4 wv  = __ldcs(((const float4*)(w + ((size_t)b * NSEQ + r) * NBOX)) + lane);
    const int4   cl  = ((const int4*)clsrow)[lane];

    float su[4]  = {sub.x, sub.y, sub.z, sub.w};
    float wa[4]  = {wv.x, wv.y, wv.z, wv.w};
    int   cla[4] = {cl.x, cl.y, cl.z, cl.w};

    float u[4];
    float mx = 0.f;
    #pragma unroll
    for (int q = 0; q < 4; q++) {
        const int box = lane * 4 + q;
        float add = 1e-6f;
        #pragma unroll
        for (int k = 0; k < NCTX; k++)
            if (cols[k] == box) add = tr[k];
        u[q] = su[q] + add * wa[q];
        mx = fmaxf(mx, fabsf(u[q]));
    }
    #pragma unroll
    for (int o = 16; o > 0; o >>= 1)
        mx = fmaxf(mx, __shfl_xor_sync(0xffffffffu, mx, o));
    const float d = (mx <= 1.f) ? 1.f : mx;

    float rr4[4];
    #pragma unroll
    for (int q = 0; q < 4; q++) {
        float vvv = u[q] / d;
        if (cla[q] == -1) vvv = -1.0f;
        rr4[q] = vvv;
    }
    float4 res;
    res.x = rr4[0]; res.y = rr4[1]; res.z = rr4[2]; res.w = rr4[3];
    __stcs(outb + r * 32 + lane, res);
}

extern "C" void kernel_launch(void* const* d_in, const int* in_sizes, int n_in,
                              void* d_out, int out_size) {
    const float* ent  = (const float*)d_in[0];   // ent_attn
    const float* spo  = (const float*)d_in[1];   // spo_attn
    const int*   ctx  = (const int*)  d_in[2];   // ctx_idx_adjusted
    const float* roi  = (const float*)d_in[3];   // roi_mask
    const int*   rcls = (const int*)  d_in[4];   // roi_cls
    const float* w    = (const float*)d_in[5];   // weight_on_children
    const int*   pidx = (const int*)  d_in[6];   // parent_idx [L,BS]
    const float* pval = (const float*)d_in[7];   // parent_valid
    const int*   cidx = (const int*)  d_in[8];   // child_idx
    const float* cval = (const float*)d_in[9];   // child_valid
    const int*   eidx = (const int*)  d_in[10];  // edge_idx
    const int*   fsmp = (const int*)  d_in[11];  // flat_sample
    const int*   fslt = (const int*)  d_in[12];  // flat_slot

    const int L = in_sizes[6] / BS;
    const int n_tasks = L * BS;

    const int threads = 256;                              // 8 warps/block
    const int blocks = (n_tasks * 32 + threads - 1) / threads;

    topdown_fused_kernel<<<blocks, threads>>>(
        ent, spo, ctx, roi, rcls, w,
        pidx, pval, cidx, cval, eidx, fsmp, fslt,
        (float*)d_out, n_tasks, L);
}